// round 1
// baseline (speedup 1.0000x reference)
#include <cuda_runtime.h>

#define IN_CH 10
#define UNITS 32
#define PILLARS 30000
#define BN_EPS 1e-3

// ---------------- device-global scratch (no runtime allocation) ----------------
__constant__ float c_W[UNITS * IN_CH];                 // raw W (for stats pass)
__constant__ float c_P[UNITS * IN_CH + 2 * UNITS];     // W'(320) | shift(32) | prelu(32)

__device__ double   g_acc[2 * UNITS];                  // [0:32) sum, [32:64) sumsq
__device__ float    g_params[UNITS * IN_CH + 2 * UNITS];
__device__ float    g_psum[PILLARS * UNITS];
__device__ unsigned g_pmax[PILLARS * UNITS];
__device__ float    g_cnt[PILLARS];
__device__ float    g_hybrid[PILLARS * UNITS];

// ---------------- helpers ----------------
__device__ __forceinline__ unsigned fkey(float f) {
    unsigned u = __float_as_uint(f);
    return (u & 0x80000000u) ? ~u : (u | 0x80000000u);
}
__device__ __forceinline__ float finv(unsigned u) {
    return __uint_as_float((u & 0x80000000u) ? (u & 0x7fffffffu) : ~u);
}

// ---------------- K0: zero accumulators ----------------
__global__ void k_init() {
    int i = blockIdx.x * blockDim.x + threadIdx.x;
    int stride = gridDim.x * blockDim.x;
    for (int j = i; j < PILLARS * UNITS; j += stride) {
        g_psum[j] = 0.0f;
        g_pmax[j] = 0u;
    }
    for (int j = i; j < PILLARS; j += stride) g_cnt[j] = 0.0f;
    if (i < 2 * UNITS) g_acc[i] = 0.0;
}

// ---------------- K1: linear + per-channel sum/sumsq ----------------
__global__ void __launch_bounds__(256) k_stats(const float* __restrict__ in, long long n) {
    float s[UNITS], q[UNITS];
#pragma unroll
    for (int c = 0; c < UNITS; c++) { s[c] = 0.0f; q[c] = 0.0f; }

    long long i0 = (long long)blockIdx.x * blockDim.x + threadIdx.x;
    long long stride = (long long)gridDim.x * blockDim.x;
    for (long long p = i0; p < n; p += stride) {
        const float* row = in + p * IN_CH;
        float r[IN_CH];
#pragma unroll
        for (int k = 0; k < IN_CH; k++) r[k] = __ldg(row + k);
#pragma unroll
        for (int c = 0; c < UNITS; c++) {
            float x = 0.0f;
#pragma unroll
            for (int k = 0; k < IN_CH; k++) x = fmaf(r[k], c_W[c * IN_CH + k], x);
            s[c] += x;
            q[c] = fmaf(x, x, q[c]);
        }
    }

    // warp reduce, then shared double, then global double atomics
    __shared__ double sh[2 * UNITS];
    int tid = threadIdx.x;
    if (tid < 2 * UNITS) sh[tid] = 0.0;
    __syncthreads();

    int lane = tid & 31;
#pragma unroll
    for (int c = 0; c < UNITS; c++) {
        float vs = s[c], vq = q[c];
#pragma unroll
        for (int off = 16; off > 0; off >>= 1) {
            vs += __shfl_down_sync(0xffffffffu, vs, off);
            vq += __shfl_down_sync(0xffffffffu, vq, off);
        }
        if (lane == 0) {
            atomicAdd(&sh[c], (double)vs);
            atomicAdd(&sh[UNITS + c], (double)vq);
        }
    }
    __syncthreads();
    if (tid < 2 * UNITS) atomicAdd(&g_acc[tid], sh[tid]);
}

// ---------------- K2: fold BN into weights ----------------
__global__ void k_finalize(const float* __restrict__ gamma,
                           const float* __restrict__ beta,
                           const float* __restrict__ prelu,
                           long long n) {
    int t = threadIdx.x;  // launched with 320 threads
    if (t >= UNITS * IN_CH) return;
    int ch = t / IN_CH;
    double invn = 1.0 / (double)n;
    double mean = g_acc[ch] * invn;
    double var  = g_acc[UNITS + ch] * invn - mean * mean;
    double rstd = 1.0 / sqrt(var + (double)BN_EPS);
    float scale = gamma[ch] * (float)rstd;
    g_params[t] = c_W[t] * scale;
    if (t % IN_CH == 0) {
        g_params[UNITS * IN_CH + ch]         = beta[ch] - (float)mean * scale;
        g_params[UNITS * IN_CH + UNITS + ch] = prelu[ch];
    }
}

// ---------------- K3: recompute, normalize, PReLU, write left half, segment atomics ----------------
__global__ void __launch_bounds__(256) k_main(const float* __restrict__ in,
                                              const int* __restrict__ inv,
                                              float* __restrict__ out,
                                              long long n) {
    long long i0 = (long long)blockIdx.x * blockDim.x + threadIdx.x;
    long long stride = (long long)gridDim.x * blockDim.x;
    for (long long p = i0; p < n; p += stride) {
        const float* row = in + p * IN_CH;
        float r[IN_CH];
#pragma unroll
        for (int k = 0; k < IN_CH; k++) r[k] = __ldg(row + k);

        int pid = inv[p];
        float*    psum = g_psum + (long long)pid * UNITS;
        unsigned* pmax = g_pmax + (long long)pid * UNITS;

        float y[UNITS];
#pragma unroll
        for (int c = 0; c < UNITS; c++) {
            float x = c_P[UNITS * IN_CH + c];  // shift (BN folded)
#pragma unroll
            for (int k = 0; k < IN_CH; k++) x = fmaf(r[k], c_P[c * IN_CH + k], x);
            float v = (x > 0.0f) ? x : c_P[UNITS * IN_CH + UNITS + c] * x;
            y[c] = v;
            atomicAdd(psum + c, v);
            atomicMax(pmax + c, fkey(v));
        }
        atomicAdd(&g_cnt[pid], 1.0f);

        float4* o = (float4*)(out + (size_t)p * 64);
#pragma unroll
        for (int j = 0; j < 8; j++) o[j] = ((float4*)y)[j];
    }
}

// ---------------- K4: per-pillar hybrid feature ----------------
__global__ void k_hybrid(const float* __restrict__ alpha) {
    float a = 1.0f / (1.0f + __expf(-alpha[0]));
    int i = blockIdx.x * blockDim.x + threadIdx.x;
    int stride = gridDim.x * blockDim.x;
    for (int j = i; j < PILLARS * UNITS; j += stride) {
        int pid = j / UNITS;
        float cnt = g_cnt[pid];
        float mean = g_psum[j] / fmaxf(cnt, 1.0f);
        float mx = (cnt > 0.0f) ? finv(g_pmax[j]) : 0.0f;
        g_hybrid[j] = a * mx + (1.0f - a) * mean;
    }
}

// ---------------- K5: gather hybrid into right half ----------------
__global__ void __launch_bounds__(256) k_gather(const int* __restrict__ inv,
                                                float* __restrict__ out,
                                                long long n) {
    long long i0 = (long long)blockIdx.x * blockDim.x + threadIdx.x;
    long long stride = (long long)gridDim.x * blockDim.x;
    for (long long p = i0; p < n; p += stride) {
        int pid = inv[p];
        const float4* h = (const float4*)(g_hybrid + (long long)pid * UNITS);
        float4* o = (float4*)(out + (size_t)p * 64 + 32);
#pragma unroll
        for (int j = 0; j < 8; j++) o[j] = h[j];
    }
}

// ---------------- launch ----------------
extern "C" void kernel_launch(void* const* d_in, const int* in_sizes, int n_in,
                              void* d_out, int out_size) {
    const float* inputs = (const float*)d_in[0];
    const float* W      = (const float*)d_in[1];
    const float* gamma  = (const float*)d_in[2];
    const float* beta   = (const float*)d_in[3];
    const float* prelu  = (const float*)d_in[4];
    const float* alpha  = (const float*)d_in[5];
    const int*   inv    = (const int*)d_in[6];
    long long n = (long long)in_sizes[0] / IN_CH;
    float* out = (float*)d_out;

    void *pW = 0, *pP = 0, *pPar = 0;
    cudaGetSymbolAddress(&pW, c_W);
    cudaGetSymbolAddress(&pP, c_P);
    cudaGetSymbolAddress(&pPar, g_params);

    // raw W -> constant bank (device-to-device async copy: graph-capturable)
    cudaMemcpyAsync(pW, W, UNITS * IN_CH * sizeof(float), cudaMemcpyDeviceToDevice, 0);

    k_init<<<512, 256>>>();
    k_stats<<<1480, 256>>>(inputs, n);
    k_finalize<<<1, 320>>>(gamma, beta, prelu, n);

    // folded params -> constant bank
    cudaMemcpyAsync(pP, pPar, (UNITS * IN_CH + 2 * UNITS) * sizeof(float),
                    cudaMemcpyDeviceToDevice, 0);

    k_main<<<2048, 256>>>(inputs, inv, out, n);
    k_hybrid<<<512, 256>>>(alpha);
    k_gather<<<2048, 256>>>(inv, out, n);
}

// round 2
// speedup vs baseline: 3.7269x; 3.7269x over previous
#include <cuda_runtime.h>

#define IN_CH 10
#define UNITS 32
#define PILLARS 30000
#define NPAR (UNITS * IN_CH + 2 * UNITS)
#define NMOM 65  /* 10 first moments + 55 unique second moments */

// ---------------- device-global scratch (no runtime allocation) ----------------
__constant__ float c_W[UNITS * IN_CH];   // raw W (stats/finalize)
__constant__ float c_P[NPAR];            // W'(320) | shift(32) | prelu(32)

__device__ double   g_acc[NMOM + 7];
__device__ float    g_params[NPAR];
__device__ float    g_psum[PILLARS * UNITS];
__device__ unsigned g_pmax[PILLARS * UNITS];
__device__ float    g_cnt[PILLARS];
__device__ float    g_hybrid[PILLARS * UNITS];

// ---------------- helpers ----------------
__device__ __forceinline__ unsigned fkey(float f) {
    unsigned u = __float_as_uint(f);
    return (u & 0x80000000u) ? ~u : (u | 0x80000000u);
}
__device__ __forceinline__ float finv(unsigned u) {
    return __uint_as_float((u & 0x80000000u) ? (u & 0x7fffffffu) : ~u);
}

// ---------------- K0: zero accumulators ----------------
__global__ void k_init() {
    int i = blockIdx.x * blockDim.x + threadIdx.x;
    int stride = gridDim.x * blockDim.x;
    for (int j = i; j < PILLARS * UNITS; j += stride) {
        g_psum[j] = 0.0f;
        g_pmax[j] = 0u;
    }
    for (int j = i; j < PILLARS; j += stride) g_cnt[j] = 0.0f;
    if (i < NMOM) g_acc[i] = 0.0;
}

// ---------------- K1: input moments (Σr, Σ r_i r_j) ----------------
__global__ void __launch_bounds__(256) k_stats(const float* __restrict__ in, long long n) {
    float s[IN_CH];
    float m[55];
#pragma unroll
    for (int k = 0; k < IN_CH; k++) s[k] = 0.0f;
#pragma unroll
    for (int k = 0; k < 55; k++) m[k] = 0.0f;

    long long i0 = (long long)blockIdx.x * blockDim.x + threadIdx.x;
    long long stride = (long long)gridDim.x * blockDim.x;
    for (long long p = i0; p < n; p += stride) {
        const float* row = in + p * IN_CH;
        float r[IN_CH];
#pragma unroll
        for (int k = 0; k < IN_CH; k++) r[k] = __ldg(row + k);
        int idx = 0;
#pragma unroll
        for (int i = 0; i < IN_CH; i++) {
            s[i] += r[i];
#pragma unroll
            for (int j = 0; j <= i; j++) { m[idx] = fmaf(r[i], r[j], m[idx]); idx++; }
        }
    }

    // warp reduce
#pragma unroll
    for (int k = 0; k < IN_CH; k++)
#pragma unroll
        for (int off = 16; off; off >>= 1) s[k] += __shfl_down_sync(0xffffffffu, s[k], off);
#pragma unroll
    for (int k = 0; k < 55; k++)
#pragma unroll
        for (int off = 16; off; off >>= 1) m[k] += __shfl_down_sync(0xffffffffu, m[k], off);

    __shared__ double sh[NMOM];
    int tid = threadIdx.x;
    for (int k = tid; k < NMOM; k += blockDim.x) sh[k] = 0.0;
    __syncthreads();
    if ((tid & 31) == 0) {
#pragma unroll
        for (int k = 0; k < IN_CH; k++) atomicAdd(&sh[k], (double)s[k]);
#pragma unroll
        for (int k = 0; k < 55; k++) atomicAdd(&sh[IN_CH + k], (double)m[k]);
    }
    __syncthreads();
    for (int k = tid; k < NMOM; k += blockDim.x) atomicAdd(&g_acc[k], sh[k]);
}

// ---------------- K2: fold BN into weights ----------------
__global__ void k_finalize(const float* __restrict__ gamma,
                           const float* __restrict__ beta,
                           const float* __restrict__ prelu,
                           long long n) {
    int c = threadIdx.x;  // launched with 32 threads
    if (c >= UNITS) return;
    double invn = 1.0 / (double)n;
    double wr[IN_CH];
    double mean = 0.0;
#pragma unroll
    for (int k = 0; k < IN_CH; k++) {
        wr[k] = (double)c_W[c * IN_CH + k];
        mean += wr[k] * g_acc[k];
    }
    mean *= invn;
    double e2 = 0.0;
    int idx = 0;
#pragma unroll
    for (int i = 0; i < IN_CH; i++)
#pragma unroll
        for (int j = 0; j <= i; j++) {
            double t = wr[i] * wr[j] * g_acc[IN_CH + idx];
            idx++;
            e2 += (i == j) ? t : 2.0 * t;
        }
    e2 *= invn;
    double var = e2 - mean * mean;
    double rstd = 1.0 / sqrt(var + 1e-3);
    float scale = gamma[c] * (float)rstd;
#pragma unroll
    for (int k = 0; k < IN_CH; k++) g_params[c * IN_CH + k] = c_W[c * IN_CH + k] * scale;
    g_params[UNITS * IN_CH + c]         = beta[c] - (float)mean * scale;
    g_params[UNITS * IN_CH + UNITS + c] = prelu[c];
}

// ---------------- K3: GEMV + PReLU, transposed coalesced atomics + left-half store ----------------
#define PAD 33
__global__ void __launch_bounds__(256) k_main(const float* __restrict__ in,
                                              const int* __restrict__ inv,
                                              float* __restrict__ out,
                                              long long n) {
    __shared__ float sy[8 * 32 * PAD];
    const int lane = threadIdx.x & 31;
    const int w = threadIdx.x >> 5;
    float* my = sy + w * 32 * PAD;

    long long gw = (long long)blockIdx.x * 8 + w;
    long long nwarps = (long long)gridDim.x * 8;

    for (long long base = gw * 32; base < n; base += nwarps * 32) {
        long long p = base + lane;
        int pid = 0;
        if (p < n) {
            const float* row = in + p * IN_CH;
            float r[IN_CH];
#pragma unroll
            for (int k = 0; k < IN_CH; k++) r[k] = __ldg(row + k);
            pid = inv[p];
#pragma unroll
            for (int c = 0; c < UNITS; c++) {
                float x = c_P[UNITS * IN_CH + c];
#pragma unroll
                for (int k = 0; k < IN_CH; k++) x = fmaf(r[k], c_P[c * IN_CH + k], x);
                float v = (x > 0.0f) ? x : c_P[UNITS * IN_CH + UNITS + c] * x;
                my[lane * PAD + c] = v;
            }
            atomicAdd(&g_cnt[pid], 1.0f);
        }
        __syncwarp();

        int nv = (int)min((long long)32, n - base);
        if (nv == 32) {
#pragma unroll
            for (int j = 0; j < 32; j++) {
                int pj = __shfl_sync(0xffffffffu, pid, j);
                float v = my[j * PAD + lane];
                long long off = (long long)pj * UNITS + lane;
                atomicAdd(g_psum + off, v);
                atomicMax(g_pmax + off, fkey(v));
                out[(size_t)(base + j) * 64 + lane] = v;
            }
        } else {
            for (int j = 0; j < nv; j++) {
                int pj = __shfl_sync(0xffffffffu, pid, j);
                float v = my[j * PAD + lane];
                long long off = (long long)pj * UNITS + lane;
                atomicAdd(g_psum + off, v);
                atomicMax(g_pmax + off, fkey(v));
                out[(size_t)(base + j) * 64 + lane] = v;
            }
        }
        __syncwarp();
    }
}

// ---------------- K4: per-pillar hybrid feature ----------------
__global__ void k_hybrid(const float* __restrict__ alpha) {
    float a = 1.0f / (1.0f + __expf(-alpha[0]));
    int i = blockIdx.x * blockDim.x + threadIdx.x;
    int stride = gridDim.x * blockDim.x;
    for (int j = i; j < PILLARS * UNITS; j += stride) {
        int pid = j >> 5;
        float cnt = g_cnt[pid];
        float mean = g_psum[j] / fmaxf(cnt, 1.0f);
        float mx = (cnt > 0.0f) ? finv(g_pmax[j]) : 0.0f;
        g_hybrid[j] = a * mx + (1.0f - a) * mean;
    }
}

// ---------------- K5: gather hybrid into right half (transposed, coalesced) ----------------
__global__ void __launch_bounds__(256) k_gather(const int* __restrict__ inv,
                                                float* __restrict__ out,
                                                long long n) {
    const int lane = threadIdx.x & 31;
    const int w = threadIdx.x >> 5;
    long long gw = (long long)blockIdx.x * 8 + w;
    long long nwarps = (long long)gridDim.x * 8;

    for (long long base = gw * 32; base < n; base += nwarps * 32) {
        long long p = base + lane;
        int pid = (p < n) ? inv[p] : 0;
        int nv = (int)min((long long)32, n - base);
        if (nv == 32) {
#pragma unroll
            for (int j = 0; j < 32; j++) {
                int pj = __shfl_sync(0xffffffffu, pid, j);
                float v = __ldg(g_hybrid + (long long)pj * UNITS + lane);
                out[(size_t)(base + j) * 64 + 32 + lane] = v;
            }
        } else {
            for (int j = 0; j < nv; j++) {
                int pj = __shfl_sync(0xffffffffu, pid, j);
                float v = __ldg(g_hybrid + (long long)pj * UNITS + lane);
                out[(size_t)(base + j) * 64 + 32 + lane] = v;
            }
        }
    }
}

// ---------------- launch ----------------
extern "C" void kernel_launch(void* const* d_in, const int* in_sizes, int n_in,
                              void* d_out, int out_size) {
    const float* inputs = (const float*)d_in[0];
    const float* W      = (const float*)d_in[1];
    const float* gamma  = (const float*)d_in[2];
    const float* beta   = (const float*)d_in[3];
    const float* prelu  = (const float*)d_in[4];
    const float* alpha  = (const float*)d_in[5];
    const int*   inv    = (const int*)d_in[6];
    long long n = (long long)in_sizes[0] / IN_CH;
    float* out = (float*)d_out;

    void *pW = 0, *pP = 0, *pPar = 0;
    cudaGetSymbolAddress(&pW, c_W);
    cudaGetSymbolAddress(&pP, c_P);
    cudaGetSymbolAddress(&pPar, g_params);

    cudaMemcpyAsync(pW, W, UNITS * IN_CH * sizeof(float), cudaMemcpyDeviceToDevice, 0);

    k_init<<<512, 256>>>();
    k_stats<<<592, 256>>>(inputs, n);
    k_finalize<<<1, 32>>>(gamma, beta, prelu, n);

    cudaMemcpyAsync(pP, pPar, NPAR * sizeof(float), cudaMemcpyDeviceToDevice, 0);

    k_main<<<2048, 256>>>(inputs, inv, out, n);
    k_hybrid<<<512, 256>>>(alpha);
    k_gather<<<2048, 256>>>(inv, out, n);
}

// round 3
// speedup vs baseline: 3.8260x; 1.0266x over previous
#include <cuda_runtime.h>

#define IN_CH 10
#define UNITS 32
#define PILLARS 30000
#define NPAR (UNITS * IN_CH + 2 * UNITS)
#define NMOM 65  /* 10 first moments + 55 unique second moments */
#define PAD 36   /* floats per point-row in smem: 144B, 16B-aligned */

// ---------------- device-global scratch (no runtime allocation) ----------------
__constant__ float c_W[UNITS * IN_CH];   // raw W (stats/finalize)
__constant__ float c_P[NPAR];            // W'(320) | shift(32) | prelu(32)

__device__ double   g_acc[NMOM + 7];
__device__ float    g_params[NPAR];
__device__ float    g_psum[PILLARS * UNITS];
__device__ unsigned g_pmax[PILLARS * UNITS];
__device__ float    g_cnt[PILLARS];
__device__ float    g_hybrid[PILLARS * UNITS];

// ---------------- helpers ----------------
__device__ __forceinline__ unsigned fkey(float f) {
    unsigned u = __float_as_uint(f);
    return (u & 0x80000000u) ? ~u : (u | 0x80000000u);
}
__device__ __forceinline__ float finv(unsigned u) {
    return __uint_as_float((u & 0x80000000u) ? (u & 0x7fffffffu) : ~u);
}
__device__ __forceinline__ void red_add_v4(float* addr, float4 v) {
    asm volatile("red.global.add.v4.f32 [%0], {%1, %2, %3, %4};"
                 :: "l"(addr), "f"(v.x), "f"(v.y), "f"(v.z), "f"(v.w) : "memory");
}

// ---------------- K0: zero accumulators ----------------
__global__ void k_init() {
    int i = blockIdx.x * blockDim.x + threadIdx.x;
    int stride = gridDim.x * blockDim.x;
    float4 z4 = make_float4(0.f, 0.f, 0.f, 0.f);
    uint4  zu = make_uint4(0u, 0u, 0u, 0u);
    for (int j = i; j < PILLARS * UNITS / 4; j += stride) {
        ((float4*)g_psum)[j] = z4;
        ((uint4*)g_pmax)[j] = zu;
    }
    for (int j = i; j < PILLARS / 4; j += stride) ((float4*)g_cnt)[j] = z4;
    if (i < NMOM) g_acc[i] = 0.0;
}

// ---------------- K1: input moments (Σr, Σ r_i r_j), paired float4 loads ----------------
__global__ void __launch_bounds__(256) k_stats(const float* __restrict__ in, long long n) {
    float s[IN_CH];
    float m[55];
#pragma unroll
    for (int k = 0; k < IN_CH; k++) s[k] = 0.0f;
#pragma unroll
    for (int k = 0; k < 55; k++) m[k] = 0.0f;

    long long i0 = (long long)blockIdx.x * blockDim.x + threadIdx.x;
    long long stride = (long long)gridDim.x * blockDim.x;
    long long npair = n >> 1;
    for (long long p2 = i0; p2 < npair; p2 += stride) {
        const float4* q = (const float4*)(in + p2 * 2 * IN_CH);
        float4 a = __ldg(q + 0), b = __ldg(q + 1), c = __ldg(q + 2),
               d = __ldg(q + 3), e = __ldg(q + 4);
        float r0[IN_CH] = {a.x, a.y, a.z, a.w, b.x, b.y, b.z, b.w, c.x, c.y};
        float r1[IN_CH] = {c.z, c.w, d.x, d.y, d.z, d.w, e.x, e.y, e.z, e.w};
        int idx = 0;
#pragma unroll
        for (int i = 0; i < IN_CH; i++) {
            s[i] += r0[i] + r1[i];
#pragma unroll
            for (int j = 0; j <= i; j++) {
                m[idx] = fmaf(r0[i], r0[j], m[idx]);
                m[idx] = fmaf(r1[i], r1[j], m[idx]);
                idx++;
            }
        }
    }
    // odd tail (n odd): one thread handles last point
    if (i0 == 0 && (n & 1)) {
        const float* row = in + (n - 1) * IN_CH;
        float r[IN_CH];
#pragma unroll
        for (int k = 0; k < IN_CH; k++) r[k] = row[k];
        int idx = 0;
#pragma unroll
        for (int i = 0; i < IN_CH; i++) {
            s[i] += r[i];
#pragma unroll
            for (int j = 0; j <= i; j++) { m[idx] = fmaf(r[i], r[j], m[idx]); idx++; }
        }
    }

    // warp reduce
#pragma unroll
    for (int k = 0; k < IN_CH; k++)
#pragma unroll
        for (int off = 16; off; off >>= 1) s[k] += __shfl_down_sync(0xffffffffu, s[k], off);
#pragma unroll
    for (int k = 0; k < 55; k++)
#pragma unroll
        for (int off = 16; off; off >>= 1) m[k] += __shfl_down_sync(0xffffffffu, m[k], off);

    __shared__ double sh[NMOM];
    int tid = threadIdx.x;
    for (int k = tid; k < NMOM; k += blockDim.x) sh[k] = 0.0;
    __syncthreads();
    if ((tid & 31) == 0) {
#pragma unroll
        for (int k = 0; k < IN_CH; k++) atomicAdd(&sh[k], (double)s[k]);
#pragma unroll
        for (int k = 0; k < 55; k++) atomicAdd(&sh[IN_CH + k], (double)m[k]);
    }
    __syncthreads();
    for (int k = tid; k < NMOM; k += blockDim.x) atomicAdd(&g_acc[k], sh[k]);
}

// ---------------- K2: fold BN into weights ----------------
__global__ void k_finalize(const float* __restrict__ gamma,
                           const float* __restrict__ beta,
                           const float* __restrict__ prelu,
                           long long n) {
    int c = threadIdx.x;  // launched with 32 threads
    if (c >= UNITS) return;
    double invn = 1.0 / (double)n;
    double wr[IN_CH];
    double mean = 0.0;
#pragma unroll
    for (int k = 0; k < IN_CH; k++) {
        wr[k] = (double)c_W[c * IN_CH + k];
        mean += wr[k] * g_acc[k];
    }
    mean *= invn;
    double e2 = 0.0;
    int idx = 0;
#pragma unroll
    for (int i = 0; i < IN_CH; i++)
#pragma unroll
        for (int j = 0; j <= i; j++) {
            double t = wr[i] * wr[j] * g_acc[IN_CH + idx];
            idx++;
            e2 += (i == j) ? t : 2.0 * t;
        }
    e2 *= invn;
    double var = e2 - mean * mean;
    double rstd = 1.0 / sqrt(var + 1e-3);
    float scale = gamma[c] * (float)rstd;
#pragma unroll
    for (int k = 0; k < IN_CH; k++) g_params[c * IN_CH + k] = c_W[c * IN_CH + k] * scale;
    g_params[UNITS * IN_CH + c]         = beta[c] - (float)mean * scale;
    g_params[UNITS * IN_CH + UNITS + c] = prelu[c];
}

// ---------------- K3: GEMV + PReLU; vector smem transpose; v4 red sum; scalar red max ----------------
__global__ void __launch_bounds__(256) k_main(const float* __restrict__ in,
                                              const int* __restrict__ inv,
                                              float* __restrict__ out,
                                              long long n) {
    __shared__ float sy[8 * 32 * PAD];
    const int lane = threadIdx.x & 31;
    const int w = threadIdx.x >> 5;
    float* my = sy + w * 32 * PAD;

    long long gw = (long long)blockIdx.x * 8 + w;
    long long nwarps = (long long)gridDim.x * 8;

    for (long long base = gw * 32; base < n; base += nwarps * 32) {
        long long p = base + lane;
        int pid = 0;
        bool valid = (p < n);
        if (valid) {
            const float* row = in + p * IN_CH;
            float r[IN_CH];
#pragma unroll
            for (int k = 0; k < IN_CH; k++) r[k] = __ldg(row + k);
            pid = inv[p];
            float y[UNITS];
#pragma unroll
            for (int c = 0; c < UNITS; c++) {
                float x = c_P[UNITS * IN_CH + c];
#pragma unroll
                for (int k = 0; k < IN_CH; k++) x = fmaf(r[k], c_P[c * IN_CH + k], x);
                y[c] = (x > 0.0f) ? x : c_P[UNITS * IN_CH + UNITS + c] * x;
            }
            // vector write of own point-row (16B aligned, stride PAD=36 words)
            float4* dst = (float4*)(my + lane * PAD);
#pragma unroll
            for (int j4 = 0; j4 < 8; j4++) dst[j4] = ((float4*)y)[j4];
            atomicAdd(&g_cnt[pid], 1.0f);
        }
        __syncwarp();

        int nv = (int)min((long long)32, n - base);
        if (nv == 32) {
            // pass 1: scalar atomicMax, lane = channel
#pragma unroll
            for (int j = 0; j < 32; j++) {
                int pj = __shfl_sync(0xffffffffu, pid, j);
                float v = my[j * PAD + lane];
                atomicMax(g_pmax + (long long)pj * UNITS + lane, fkey(v));
            }
            // pass 2: v4 red sum + STG.128 left half; 4 points per pass
            int jq = lane >> 3;          // point within quad
            int c4 = (lane & 7) * 4;     // channel group
#pragma unroll
            for (int jj = 0; jj < 8; jj++) {
                int j = jj * 4 + jq;
                int pj = __shfl_sync(0xffffffffu, pid, j);
                float4 v = *(float4*)(my + j * PAD + c4);
                red_add_v4(g_psum + (long long)pj * UNITS + c4, v);
                *(float4*)(out + (size_t)(base + j) * 64 + c4) = v;
            }
        } else {
            for (int j = 0; j < nv; j++) {
                int pj = __shfl_sync(0xffffffffu, pid, j);
                float v = my[j * PAD + lane];
                long long off = (long long)pj * UNITS + lane;
                atomicAdd(g_psum + off, v);
                atomicMax(g_pmax + off, fkey(v));
                out[(size_t)(base + j) * 64 + lane] = v;
            }
        }
        __syncwarp();
    }
}

// ---------------- K4: per-pillar hybrid feature (vectorized) ----------------
__global__ void k_hybrid(const float* __restrict__ alpha) {
    float a = 1.0f / (1.0f + __expf(-alpha[0]));
    int i = blockIdx.x * blockDim.x + threadIdx.x;
    int stride = gridDim.x * blockDim.x;
    for (int j4 = i; j4 < PILLARS * UNITS / 4; j4 += stride) {
        int pid = j4 >> 3;
        float cnt = g_cnt[pid];
        float4 sm = ((float4*)g_psum)[j4];
        uint4 mu = ((uint4*)g_pmax)[j4];
        float rc = 1.0f / fmaxf(cnt, 1.0f);
        bool has = (cnt > 0.0f);
        float4 h;
        h.x = a * (has ? finv(mu.x) : 0.0f) + (1.0f - a) * sm.x * rc;
        h.y = a * (has ? finv(mu.y) : 0.0f) + (1.0f - a) * sm.y * rc;
        h.z = a * (has ? finv(mu.z) : 0.0f) + (1.0f - a) * sm.z * rc;
        h.w = a * (has ? finv(mu.w) : 0.0f) + (1.0f - a) * sm.w * rc;
        ((float4*)g_hybrid)[j4] = h;
    }
}

// ---------------- K5: gather hybrid into right half (vectorized transposed) ----------------
__global__ void __launch_bounds__(256) k_gather(const int* __restrict__ inv,
                                                float* __restrict__ out,
                                                long long n) {
    const int lane = threadIdx.x & 31;
    const int w = threadIdx.x >> 5;
    long long gw = (long long)blockIdx.x * 8 + w;
    long long nwarps = (long long)gridDim.x * 8;

    for (long long base = gw * 32; base < n; base += nwarps * 32) {
        long long p = base + lane;
        int pid = (p < n) ? inv[p] : 0;
        int nv = (int)min((long long)32, n - base);
        if (nv == 32) {
            int jq = lane >> 3;
            int c4 = (lane & 7) * 4;
#pragma unroll
            for (int jj = 0; jj < 8; jj++) {
                int j = jj * 4 + jq;
                int pj = __shfl_sync(0xffffffffu, pid, j);
                float4 v = __ldg((const float4*)(g_hybrid + (long long)pj * UNITS + c4));
                *(float4*)(out + (size_t)(base + j) * 64 + 32 + c4) = v;
            }
        } else {
            for (int j = 0; j < nv; j++) {
                int pj = __shfl_sync(0xffffffffu, pid, j);
                float v = __ldg(g_hybrid + (long long)pj * UNITS + lane);
                out[(size_t)(base + j) * 64 + 32 + lane] = v;
            }
        }
    }
}

// ---------------- launch ----------------
extern "C" void kernel_launch(void* const* d_in, const int* in_sizes, int n_in,
                              void* d_out, int out_size) {
    const float* inputs = (const float*)d_in[0];
    const float* W      = (const float*)d_in[1];
    const float* gamma  = (const float*)d_in[2];
    const float* beta   = (const float*)d_in[3];
    const float* prelu  = (const float*)d_in[4];
    const float* alpha  = (const float*)d_in[5];
    const int*   inv    = (const int*)d_in[6];
    long long n = (long long)in_sizes[0] / IN_CH;
    float* out = (float*)d_out;

    void *pW = 0, *pP = 0, *pPar = 0;
    cudaGetSymbolAddress(&pW, c_W);
    cudaGetSymbolAddress(&pP, c_P);
    cudaGetSymbolAddress(&pPar, g_params);

    cudaMemcpyAsync(pW, W, UNITS * IN_CH * sizeof(float), cudaMemcpyDeviceToDevice, 0);

    k_init<<<512, 256>>>();
    k_stats<<<592, 256>>>(inputs, n);
    k_finalize<<<1, 32>>>(gamma, beta, prelu, n);

    cudaMemcpyAsync(pP, pPar, NPAR * sizeof(float), cudaMemcpyDeviceToDevice, 0);

    k_main<<<2048, 256>>>(inputs, inv, out, n);
    k_hybrid<<<512, 256>>>(alpha);
    k_gather<<<2048, 256>>>(inv, out, n);
}